// round 2
// baseline (speedup 1.0000x reference)
#include <cuda_runtime.h>
#include <math.h>

#define NB      32
#define SAMPLES 5000
#define HW      (512 * 1024)
#define TOTAL   (NB * SAMPLES)
#define SIGMA   0.03f
#define EPS     1e-6f

// scratch accumulators: [0]=equal_loss, [1]=unequal_loss, [2]=valid_samples
__device__ float g_acc[3];

__global__ void rl_init_kernel() {
    g_acc[0] = 0.0f;
    g_acc[1] = 0.0f;
    g_acc[2] = 0.0f;
}

__global__ void __launch_bounds__(256) rl_main_kernel(
    const float* __restrict__ pred,
    const float* __restrict__ targ,
    const int*   __restrict__ mask,   // bool upcast to int32 by harness
    const int*   __restrict__ idxA,
    const int*   __restrict__ idxB)
{
    int i = blockIdx.x * blockDim.x + threadIdx.x;

    float eq = 0.0f, uneq = 0.0f, valid = 0.0f;

    if (i < TOTAL) {
        int n = i / SAMPLES;
        long long base = (long long)n * (long long)HW;
        int a = idxA[i];
        int b = idxB[i];
        long long ia = base + (long long)a;
        long long ib = base + (long long)b;

        int mA = mask[ia];
        int mB = mask[ib];

        if (mA && mB) {
            valid = 1.0f;
            float tA = targ[ia];
            float tB = targ[ib];
            float ratio = tA / (tB + EPS);
            const float hi = 1.0f + SIGMA;
            const float lo = 1.0f / (1.0f + SIGMA);

            float pA = pred[ia];
            float pB = pred[ib];

            if (ratio < hi && ratio > lo) {
                float d = pA - pB;
                eq = d * d;
            } else {
                float label = (ratio >= hi) ? 1.0f : -1.0f;
                float x = (pB - pA) * label;
                // matches reference log1p(exp(x)) in fp32; stable guard for large x
                uneq = (x > 20.0f) ? x : log1pf(expf(x));
            }
        }
    }

    // --- block reduction of (eq, uneq, valid) ---
    #pragma unroll
    for (int off = 16; off > 0; off >>= 1) {
        eq    += __shfl_down_sync(0xffffffffu, eq,    off);
        uneq  += __shfl_down_sync(0xffffffffu, uneq,  off);
        valid += __shfl_down_sync(0xffffffffu, valid, off);
    }

    __shared__ float s_eq[8], s_uneq[8], s_valid[8];
    int lane = threadIdx.x & 31;
    int wid  = threadIdx.x >> 5;
    if (lane == 0) {
        s_eq[wid]    = eq;
        s_uneq[wid]  = uneq;
        s_valid[wid] = valid;
    }
    __syncthreads();

    if (wid == 0) {
        int nwarps = (blockDim.x + 31) >> 5;
        eq    = (lane < nwarps) ? s_eq[lane]    : 0.0f;
        uneq  = (lane < nwarps) ? s_uneq[lane]  : 0.0f;
        valid = (lane < nwarps) ? s_valid[lane] : 0.0f;
        #pragma unroll
        for (int off = 4; off > 0; off >>= 1) {
            eq    += __shfl_down_sync(0xffffffffu, eq,    off);
            uneq  += __shfl_down_sync(0xffffffffu, uneq,  off);
            valid += __shfl_down_sync(0xffffffffu, valid, off);
        }
        if (lane == 0) {
            atomicAdd(&g_acc[0], eq);
            atomicAdd(&g_acc[1], uneq);
            atomicAdd(&g_acc[2], valid);
        }
    }
}

__global__ void rl_final_kernel(float* __restrict__ out) {
    // ALPHA = 1.0, LOSS_WEIGHT = 1.0
    out[0] = (g_acc[0] + g_acc[1]) / (g_acc[2] + EPS);
}

extern "C" void kernel_launch(void* const* d_in, const int* in_sizes, int n_in,
                              void* d_out, int out_size)
{
    const float* pred = (const float*)d_in[0];
    const float* targ = (const float*)d_in[1];
    const int*   mask = (const int*)d_in[2];
    const int*   idxA = (const int*)d_in[3];
    const int*   idxB = (const int*)d_in[4];
    float* out = (float*)d_out;

    rl_init_kernel<<<1, 1>>>();
    const int threads = 256;
    const int blocks = (TOTAL + threads - 1) / threads;   // 625
    rl_main_kernel<<<blocks, threads>>>(pred, targ, mask, idxA, idxB);
    rl_final_kernel<<<1, 1>>>(out);
}